// round 1
// baseline (speedup 1.0000x reference)
#include <cuda_runtime.h>
#include <cuda_bf16.h>
#include <cstddef>

// Problem constants (CTCLoss_56298431315981): T=1024, B=32, C=1024, L=128
constexpr int kT = 1024;
constexpr int kB = 32;
constexpr int kC = 1024;
constexpr int kL = 128;
constexpr int kS = 2 * kL + 1;   // 257 extended states
constexpr int kStride = 132;     // per-(b,t) emission row: 128 labels + blank @128, pad to 132

// Scratch (static __device__ — no allocations allowed)
__device__ float g_E[(size_t)kB * kT * kStride]; // emissions: [b][t][k]; k<128 labels, k=128 blank
__device__ float g_nll[kB];

// ---------------------------------------------------------------------------
// Kernel 1: per-(t,b) log-softmax normalizer + gather of needed emissions.
// One warp per row. 8 warps / 256 threads per block.
// ---------------------------------------------------------------------------
__global__ void __launch_bounds__(256) ctc_emis_kernel(
    const float* __restrict__ data, const int* __restrict__ labels)
{
    __shared__ float sh[8][kC];
    const int warp = threadIdx.x >> 5;
    const int lane = threadIdx.x & 31;
    const int row  = (blockIdx.x << 3) + warp;   // 0 .. T*B-1
    const int t = row >> 5;                      // B == 32
    const int b = row & 31;

    const float4* src = reinterpret_cast<const float4*>(data + (size_t)row * kC);

    float m = -3.4e38f;
    float4 v[8];
#pragma unroll
    for (int i = 0; i < 8; i++) {
        v[i] = src[(i << 5) + lane];
        reinterpret_cast<float4*>(sh[warp])[(i << 5) + lane] = v[i];
        m = fmaxf(m, fmaxf(fmaxf(v[i].x, v[i].y), fmaxf(v[i].z, v[i].w)));
    }
#pragma unroll
    for (int o = 16; o; o >>= 1) m = fmaxf(m, __shfl_xor_sync(0xffffffffu, m, o));

    float ssum = 0.f;
#pragma unroll
    for (int i = 0; i < 8; i++) {
        ssum += __expf(v[i].x - m) + __expf(v[i].y - m) +
                __expf(v[i].z - m) + __expf(v[i].w - m);
    }
#pragma unroll
    for (int o = 16; o; o >>= 1) ssum += __shfl_xor_sync(0xffffffffu, ssum, o);

    const float lse = m + __logf(ssum);

    __syncwarp();  // order smem row stores before cross-lane gather

    const int* lab = labels + b * kL;
    float* dst = g_E + ((size_t)b * kT + t) * kStride;
#pragma unroll
    for (int k0 = 0; k0 < kL; k0 += 32) {
        const int k = k0 + lane;
        dst[k] = sh[warp][lab[k]] - lse;
    }
    if (lane == 0) dst[kL] = sh[warp][0] - lse;  // blank (class 0)
}

// ---------------------------------------------------------------------------
// Kernel 2: CTC forward DP. One CTA per batch element, thread s = state s.
// Double-buffered alpha in smem, 1 barrier per time step, prefetch next emit.
// ---------------------------------------------------------------------------
__global__ void __launch_bounds__(288) ctc_dp_kernel(
    const int* __restrict__ labels, const int* __restrict__ llen,
    const int* __restrict__ dlen)
{
    __shared__ float A[2][264];
    const int b = blockIdx.x;
    const int s = threadIdx.x;

    const int len  = llen[b];
    const int Tb   = dlen[b];
    const int smax = 2 * len;            // final blank state index (<= 256)
    const bool doit = (s <= smax);       // states beyond smax never influence result
    const bool odd  = (s & 1) != 0;
    const int  k    = s >> 1;
    const int  eoff = odd ? k : kL;      // odd state 2k+1 -> label k, even -> blank

    const float* __restrict__ Eb = g_E + (size_t)b * kT * kStride;

    // skip transition legal only for odd s>=3 with label[k] != label[k-1]
    bool allow = false;
    if (odd && s >= 3) {
        const int* lab = labels + b * kL;
        allow = (lab[k] != lab[k - 1]);
    }

    const float NEG = -1e30f;

    if (doit) A[0][s] = (s < 2) ? __ldg(&Eb[eoff]) : NEG;
    __syncthreads();

    int cur = 0;
    float e = doit ? __ldg(&Eb[kStride + eoff]) : 0.f;  // emission at t=1 (Tb >= 512)

    for (int t = 1; t < Tb; ++t) {
        float e_next = 0.f;
        if (doit && (t + 1) < Tb) e_next = __ldg(&Eb[(size_t)(t + 1) * kStride + eoff]);

        if (doit) {
            const float a0 = A[cur][s];
            const float a1 = (s >= 1) ? A[cur][s - 1] : NEG;
            const float a2 = allow    ? A[cur][s - 2] : NEG;
            const float mm = fmaxf(a0, fmaxf(a1, a2));
            const float vv = __expf(a0 - mm) + __expf(a1 - mm) + __expf(a2 - mm);
            A[cur ^ 1][s] = mm + __logf(vv) + e;
        }
        __syncthreads();
        cur ^= 1;
        e = e_next;
    }

    if (s == 0) {
        const float ab = A[cur][smax];
        const float al = A[cur][smax - 1];
        const float mm = fmaxf(ab, al);
        g_nll[b] = -(mm + __logf(__expf(ab - mm) + __expf(al - mm)));
    }
}

// ---------------------------------------------------------------------------
// Kernel 3: mean over batch -> d_out[0]. Deterministic (no atomics).
// ---------------------------------------------------------------------------
__global__ void ctc_finish_kernel(float* __restrict__ out)
{
    float v = g_nll[threadIdx.x];
#pragma unroll
    for (int o = 16; o; o >>= 1) v += __shfl_xor_sync(0xffffffffu, v, o);
    if (threadIdx.x == 0) out[0] = v * (1.0f / kB);
}

extern "C" void kernel_launch(void* const* d_in, const int* in_sizes, int n_in,
                              void* d_out, int out_size)
{
    const int*   labels       = (const int*)d_in[0];
    const float* data         = (const float*)d_in[1];
    const int*   label_length = (const int*)d_in[2];
    const int*   data_length  = (const int*)d_in[3];
    float*       out          = (float*)d_out;

    // 1) emissions: one warp per (t,b) row; T*B/8 blocks of 256 threads
    ctc_emis_kernel<<<(kT * kB) / 8, 256>>>(data, labels);
    // 2) serial-in-T forward DP: one CTA per batch element
    ctc_dp_kernel<<<kB, 288>>>(labels, label_length, data_length);
    // 3) mean reduction
    ctc_finish_kernel<<<1, 32>>>(out);
}

// round 3
// speedup vs baseline: 1.6667x; 1.6667x over previous
#include <cuda_runtime.h>
#include <cuda_bf16.h>
#include <cstddef>

// Problem constants (CTCLoss_56298431315981): T=1024, B=32, C=1024, L=128
constexpr int kT = 1024;
constexpr int kB = 32;
constexpr int kC = 1024;
constexpr int kL = 128;
constexpr int kS = 2 * kL + 1;   // 257 extended states
constexpr int kRow = 384;        // expanded emission row: 32 lanes x 12 floats

// Scratch (static __device__ — no allocations allowed)
__device__ float g_E2[(size_t)kB * kT * kRow]; // per-state probs, [b][t][lane*12+j]
__device__ float g_nll[kB];

// ---------------------------------------------------------------------------
// 2^d as a product of two representable fp32 powers of two. |d|<=252 exact;
// d<-252 flushes to 0 (value provably negligible at that frame gap).
// ---------------------------------------------------------------------------
__device__ __forceinline__ void twoFactor(int d, float& f1, float& f2)
{
    d = max(min(d, 252), -300);
    if (d < -252) { f1 = 0.f; f2 = 0.f; return; }
    const int dh = d / 2;  // trunc toward 0: both halves stay in [-126,126]
    f1 = __int_as_float((dh + 127) << 23);
    f2 = __int_as_float((d - dh + 127) << 23);
}

// ---------------------------------------------------------------------------
// Kernel 1: per-(t,b) softmax; write linear-domain per-STATE probabilities,
// expanded so the DP kernel loads 3 float4 per lane. One warp per row.
// ---------------------------------------------------------------------------
__global__ void __launch_bounds__(256) ctc_emis_kernel(
    const float* __restrict__ data, const int* __restrict__ labels)
{
    __shared__ float sh[8][kC];
    __shared__ int   shlab[8][kL];
    const int warp = threadIdx.x >> 5;
    const int lane = threadIdx.x & 31;
    const int row  = (blockIdx.x << 3) + warp;   // 0 .. T*B-1
    const int t = row >> 5;                      // B == 32
    const int b = row & 31;

    // stage this b's labels (128 ints = 32 lanes x int4)
    reinterpret_cast<int4*>(shlab[warp])[lane] =
        reinterpret_cast<const int4*>(labels + b * kL)[lane];

    const float4* src = reinterpret_cast<const float4*>(data + (size_t)row * kC);

    float m = -3.4e38f;
    float4 v[8];
#pragma unroll
    for (int i = 0; i < 8; i++) {
        v[i] = src[(i << 5) + lane];
        reinterpret_cast<float4*>(sh[warp])[(i << 5) + lane] = v[i];
        m = fmaxf(m, fmaxf(fmaxf(v[i].x, v[i].y), fmaxf(v[i].z, v[i].w)));
    }
#pragma unroll
    for (int o = 16; o; o >>= 1) m = fmaxf(m, __shfl_xor_sync(0xffffffffu, m, o));

    float ssum = 0.f;
#pragma unroll
    for (int i = 0; i < 8; i++) {
        ssum += __expf(v[i].x - m) + __expf(v[i].y - m) +
                __expf(v[i].z - m) + __expf(v[i].w - m);
    }
#pragma unroll
    for (int o = 16; o; o >>= 1) ssum += __shfl_xor_sync(0xffffffffu, ssum, o);

    const float lse = m + __logf(ssum);

    __syncwarp();  // smem stores (data row + labels) visible warp-wide

    const float blank = __expf(sh[warp][0] - lse);   // class 0 = blank
    float out[12];
#pragma unroll
    for (int j = 0; j < 12; j++) out[j] = 0.f;
    const int s0 = 9 * lane;
#pragma unroll
    for (int j = 0; j < 9; j++) {
        const int s = s0 + j;
        if (s < kS) {
            if (s & 1) out[j] = __expf(sh[warp][shlab[warp][s >> 1]] - lse);
            else       out[j] = blank;
        }
    }
    float4* dst = reinterpret_cast<float4*>(
        g_E2 + ((size_t)b * kT + t) * kRow + lane * 12);
    dst[0] = make_float4(out[0], out[1], out[2],  out[3]);
    dst[1] = make_float4(out[4], out[5], out[6],  out[7]);
    dst[2] = make_float4(out[8], out[9], out[10], out[11]);
}

// ---------------------------------------------------------------------------
// Kernel 2: CTC forward DP, linear domain, per-lane block floating point with
// a frame-gap cap. One warp per batch element, lane l owns states [9l, 9l+9).
// No barriers, no MUFU in the inner loop.
// ---------------------------------------------------------------------------
__global__ void __launch_bounds__(32) ctc_dp_kernel(
    const int* __restrict__ labels, const int* __restrict__ llen,
    const int* __restrict__ dlen)
{
    const unsigned FULL = 0xffffffffu;
    const int NEGI = -(1 << 28);
    const int b    = blockIdx.x;
    const int lane = threadIdx.x;

    const int len = llen[b];
    const int Tb  = dlen[b];               // 512..1024
    const float* __restrict__ Eb = g_E2 + (size_t)b * kT * kRow;
    const int* __restrict__ lab  = labels + b * kL;

    // skip-transition legality per owned state
    float allow[9];
#pragma unroll
    for (int j = 0; j < 9; j++) {
        const int s = 9 * lane + j;
        bool al = false;
        if (s < kS && (s & 1) && s >= 3) al = (lab[s >> 1] != lab[(s >> 1) - 1]);
        allow[j] = al ? 1.0f : 0.0f;
    }

    float a[9];
#pragma unroll
    for (int j = 0; j < 9; j++) a[j] = 0.f;
    if (lane == 0) {
        a[0] = __ldg(&Eb[0]);    // t=0 state 0 (blank)
        a[1] = __ldg(&Eb[1]);    // t=0 state 1 (label 0)
    }
    int   X   = 0;
    float sD1 = (lane == 0) ? 0.f : 1.f;   // halo frame factor = sD1*sD2
    float sD2 = (lane == 0) ? 0.f : 1.f;

    // 4-deep emission prefetch ring (rows t=1..4; Tb >= 512)
    float4 P[4][3];
#pragma unroll
    for (int q = 0; q < 4; q++) {
        const float4* r = reinterpret_cast<const float4*>(
            Eb + (size_t)(1 + q) * kRow + lane * 12);
        P[q][0] = __ldg(r); P[q][1] = __ldg(r + 1); P[q][2] = __ldg(r + 2);
    }

    auto dostep = [&](const float4* Pq) {
        float h1 = __shfl_up_sync(FULL, a[8], 1);
        float h2 = __shfl_up_sync(FULL, a[7], 1);
        h1 = (h1 * sD1) * sD2;                     // alpha[s0-1] in local frame
        h2 = (h2 * sD1) * sD2;                     // alpha[s0-2] in local frame
        float na[9];
        na[0] = fmaf(allow[0], h2,   a[0] + h1)   * Pq[0].x;
        na[1] = fmaf(allow[1], h1,   a[1] + a[0]) * Pq[0].y;
        na[2] = fmaf(allow[2], a[0], a[2] + a[1]) * Pq[0].z;
        na[3] = fmaf(allow[3], a[1], a[3] + a[2]) * Pq[0].w;
        na[4] = fmaf(allow[4], a[2], a[4] + a[3]) * Pq[1].x;
        na[5] = fmaf(allow[5], a[3], a[5] + a[4]) * Pq[1].y;
        na[6] = fmaf(allow[6], a[4], a[6] + a[5]) * Pq[1].z;
        na[7] = fmaf(allow[7], a[5], a[7] + a[6]) * Pq[1].w;
        na[8] = fmaf(allow[8], a[6], a[8] + a[7]) * Pq[2].x;
#pragma unroll
        for (int j = 0; j < 9; j++) a[j] = na[j];
    };

    auto prefetch = [&](float4* Pq, int trow) {
        const float4* r = reinterpret_cast<const float4*>(
            Eb + (size_t)trow * kRow + lane * 12);
        Pq[0] = __ldg(r); Pq[1] = __ldg(r + 1); Pq[2] = __ldg(r + 2);
    };

    auto rescale = [&]() {
        float m = a[0];
#pragma unroll
        for (int j = 1; j < 9; j++) m = fmaxf(m, a[j]);
        const bool nz = (m > 0.f);
        const int  e    = nz ? (((__float_as_int(m) >> 23) & 0xff) - 127) : 0;
        const int  cand = nz ? (X + e) : NEGI;
        const int  candp = __shfl_up_sync(FULL, cand, 1);
        int Xn;
        if (lane == 0) {
            Xn = nz ? cand : X;
        } else {
            const int lower = (candp > NEGI) ? (candp - 24) : NEGI;
            const int ownc  = nz ? cand : NEGI;
            Xn = max(ownc, lower);
            if (Xn == NEGI) Xn = X;                // fully empty region: keep
        }
        float f1, f2;
        twoFactor(X - Xn, f1, f2);                 // rescale own values
#pragma unroll
        for (int j = 0; j < 9; j++) a[j] = (a[j] * f1) * f2;
        X = Xn;
        const int Xp = __shfl_up_sync(FULL, X, 1); // predecessor FINAL frame
        twoFactor(Xp - X, sD1, sD2);
        if (lane == 0) { sD1 = 0.f; sD2 = 0.f; }
    };

    int t = 1;
    for (; t + 3 < Tb; t += 4) {
        dostep(P[0]); prefetch(P[0], min(t + 4, kT - 1));
        dostep(P[1]); prefetch(P[1], min(t + 5, kT - 1));
        dostep(P[2]); prefetch(P[2], min(t + 6, kT - 1));
        dostep(P[3]); prefetch(P[3], min(t + 7, kT - 1));
        rescale();
    }
    for (int q = 0; t < Tb; ++t, ++q) dostep(P[q]);

    // Final: combine alpha[2*len] and alpha[2*len-1] with per-lane exponents.
    __shared__ float Af[288];
    __shared__ int   Xf[32];
#pragma unroll
    for (int j = 0; j < 9; j++) Af[9 * lane + j] = a[j];
    Xf[lane] = X;
    __syncwarp();
    if (lane == 0) {
        const int sB = 2 * len, sL = sB - 1;
        const float aB = Af[sB], aL = Af[sL];
        const float yB = (aB > 0.f) ? (log2f(aB) + (float)Xf[sB / 9]) : -1e30f;
        const float yL = (aL > 0.f) ? (log2f(aL) + (float)Xf[sL / 9]) : -1e30f;
        const float mx = fmaxf(yB, yL);
        const float r  = mx + log2f(exp2f(yB - mx) + exp2f(yL - mx));
        g_nll[b] = -r * 0.69314718055994530942f;   // log2 -> ln
    }
}

// ---------------------------------------------------------------------------
// Kernel 3: mean over batch -> d_out[0]. Deterministic (no atomics).
// ---------------------------------------------------------------------------
__global__ void ctc_finish_kernel(float* __restrict__ out)
{
    float v = g_nll[threadIdx.x];
#pragma unroll
    for (int o = 16; o; o >>= 1) v += __shfl_xor_sync(0xffffffffu, v, o);
    if (threadIdx.x == 0) out[0] = v * (1.0f / kB);
}

extern "C" void kernel_launch(void* const* d_in, const int* in_sizes, int n_in,
                              void* d_out, int out_size)
{
    const int*   labels       = (const int*)d_in[0];
    const float* data         = (const float*)d_in[1];
    const int*   label_length = (const int*)d_in[2];
    const int*   data_length  = (const int*)d_in[3];
    float*       out          = (float*)d_out;

    ctc_emis_kernel<<<(kT * kB) / 8, 256>>>(data, labels);
    ctc_dp_kernel<<<kB, 32>>>(labels, label_length, data_length);
    ctc_finish_kernel<<<1, 32>>>(out);
}

// round 4
// speedup vs baseline: 2.2036x; 1.3221x over previous
#include <cuda_runtime.h>
#include <cuda_bf16.h>
#include <cstddef>

// Problem constants (CTCLoss_56298431315981): T=1024, B=32, C=1024, L=128
constexpr int kT = 1024;
constexpr int kB = 32;
constexpr int kC = 1024;
constexpr int kL = 128;
constexpr int kS = 2 * kL + 1;   // 257 extended states
constexpr int kRow = 384;        // floats per (b,t) row: 3 comps x 32 lanes x 4

// Scratch (static __device__ — no allocations allowed)
// Layout: float4 view [b][t][comp 0..2][lane 0..31]; lane-major within comp so
// each DP LDG.128 reads 512 contiguous bytes (4 lines).
__device__ float g_E2[(size_t)kB * kT * kRow];
__device__ float g_nll[kB];

// ---------------------------------------------------------------------------
// 2^d as a product of two representable fp32 powers of two. |d|<=252 exact;
// d<-252 flushes to 0. NOTE: factors must stay separate (product can be inf;
// 0 * f1 * f2 must remain 0 for empty-lane halos).
// ---------------------------------------------------------------------------
__device__ __forceinline__ void twoFactor(int d, float& f1, float& f2)
{
    d = max(min(d, 252), -300);
    if (d < -252) { f1 = 0.f; f2 = 0.f; return; }
    const int dh = d / 2;  // trunc toward 0: both halves stay in [-126,126]
    f1 = __int_as_float((dh + 127) << 23);
    f2 = __int_as_float((d - dh + 127) << 23);
}

// ---------------------------------------------------------------------------
// Kernel 1: per-(t,b) softmax; write linear-domain per-STATE probabilities in
// lane-major layout. One warp per row.
// ---------------------------------------------------------------------------
__global__ void __launch_bounds__(256) ctc_emis_kernel(
    const float* __restrict__ data, const int* __restrict__ labels)
{
    __shared__ float sh[8][kC];
    __shared__ int   shlab[8][kL];
    const int warp = threadIdx.x >> 5;
    const int lane = threadIdx.x & 31;
    const int row  = (blockIdx.x << 3) + warp;   // 0 .. T*B-1
    const int t = row >> 5;                      // B == 32
    const int b = row & 31;

    reinterpret_cast<int4*>(shlab[warp])[lane] =
        reinterpret_cast<const int4*>(labels + b * kL)[lane];

    const float4* src = reinterpret_cast<const float4*>(data + (size_t)row * kC);

    float m = -3.4e38f;
    float4 v[8];
#pragma unroll
    for (int i = 0; i < 8; i++) {
        v[i] = src[(i << 5) + lane];
        reinterpret_cast<float4*>(sh[warp])[(i << 5) + lane] = v[i];
        m = fmaxf(m, fmaxf(fmaxf(v[i].x, v[i].y), fmaxf(v[i].z, v[i].w)));
    }
#pragma unroll
    for (int o = 16; o; o >>= 1) m = fmaxf(m, __shfl_xor_sync(0xffffffffu, m, o));

    float ssum = 0.f;
#pragma unroll
    for (int i = 0; i < 8; i++) {
        ssum += __expf(v[i].x - m) + __expf(v[i].y - m) +
                __expf(v[i].z - m) + __expf(v[i].w - m);
    }
#pragma unroll
    for (int o = 16; o; o >>= 1) ssum += __shfl_xor_sync(0xffffffffu, ssum, o);

    const float lse = m + __logf(ssum);

    __syncwarp();  // smem stores (data row + labels) visible warp-wide

    const float blank = __expf(sh[warp][0] - lse);   // class 0 = blank
    float out[12];
#pragma unroll
    for (int j = 0; j < 12; j++) out[j] = 0.f;
    const int s0 = 9 * lane;
#pragma unroll
    for (int j = 0; j < 9; j++) {
        const int s = s0 + j;
        if (s < kS) {
            if (s & 1) out[j] = __expf(sh[warp][shlab[warp][s >> 1]] - lse);
            else       out[j] = blank;
        }
    }
    float4* dst = reinterpret_cast<float4*>(g_E2 + ((size_t)b * kT + t) * kRow);
    dst[lane]      = make_float4(out[0], out[1], out[2],  out[3]);
    dst[32 + lane] = make_float4(out[4], out[5], out[6],  out[7]);
    dst[64 + lane] = make_float4(out[8], out[9], out[10], out[11]);
}

// ---------------------------------------------------------------------------
// Kernel 2: CTC forward DP, linear domain, per-lane block floating point with
// a frame-gap cap. One warp per batch element, lane l owns states [9l, 9l+9).
// No barriers, no MUFU, no local memory in the inner loop.
// ---------------------------------------------------------------------------
__global__ void __launch_bounds__(32) ctc_dp_kernel(
    const int* __restrict__ labels, const int* __restrict__ llen,
    const int* __restrict__ dlen)
{
    const unsigned FULL = 0xffffffffu;
    const int NEGI = -(1 << 28);
    const int b    = blockIdx.x;
    const int lane = threadIdx.x;

    const int len = llen[b];
    const int Tb  = dlen[b];               // 512..1024
    const float* __restrict__ Eb = g_E2 + (size_t)b * kT * kRow;
    const int* __restrict__ lab  = labels + b * kL;

    float allow[9];
#pragma unroll
    for (int j = 0; j < 9; j++) {
        const int s = 9 * lane + j;
        bool al = false;
        if (s < kS && (s & 1) && s >= 3) al = (lab[s >> 1] != lab[(s >> 1) - 1]);
        allow[j] = al ? 1.0f : 0.0f;
    }

    float a[9];
#pragma unroll
    for (int j = 0; j < 9; j++) a[j] = 0.f;
    if (lane == 0) {
        a[0] = __ldg(&Eb[0]);    // t=0 state 0 (blank)  [comp0 lane0 .x]
        a[1] = __ldg(&Eb[1]);    // t=0 state 1 (label0) [comp0 lane0 .y]
    }
    int   X   = 0;
    float sD1 = (lane == 0) ? 0.f : 1.f;   // halo frame factor = sD1*sD2 (keep split!)
    float sD2 = (lane == 0) ? 0.f : 1.f;

    // 8-deep emission prefetch ring (rows t=1..8; Tb >= 512 so all valid)
    float4 P[8][3];
#pragma unroll
    for (int q = 0; q < 8; q++) {
        const float4* r = reinterpret_cast<const float4*>(Eb + (size_t)(1 + q) * kRow);
        P[q][0] = __ldg(r + lane);
        P[q][1] = __ldg(r + 32 + lane);
        P[q][2] = __ldg(r + 64 + lane);
    }

    auto dostep = [&](const float4* Pq) {
        float h1 = __shfl_up_sync(FULL, a[8], 1);
        float h2 = __shfl_up_sync(FULL, a[7], 1);
        h1 = (h1 * sD1) * sD2;                     // alpha[s0-1] in local frame
        h2 = (h2 * sD1) * sD2;                     // alpha[s0-2] in local frame
        float na[9];
        na[0] = fmaf(allow[0], h2,   a[0] + h1)   * Pq[0].x;
        na[1] = fmaf(allow[1], h1,   a[1] + a[0]) * Pq[0].y;
        na[2] = fmaf(allow[2], a[0], a[2] + a[1]) * Pq[0].z;
        na[3] = fmaf(allow[3], a[1], a[3] + a[2]) * Pq[0].w;
        na[4] = fmaf(allow[4], a[2], a[4] + a[3]) * Pq[1].x;
        na[5] = fmaf(allow[5], a[3], a[5] + a[4]) * Pq[1].y;
        na[6] = fmaf(allow[6], a[4], a[6] + a[5]) * Pq[1].z;
        na[7] = fmaf(allow[7], a[5], a[7] + a[6]) * Pq[1].w;
        na[8] = fmaf(allow[8], a[6], a[8] + a[7]) * Pq[2].x;
#pragma unroll
        for (int j = 0; j < 9; j++) a[j] = na[j];
    };

    auto prefetch = [&](float4* Pq, int trow) {
        const float4* r = reinterpret_cast<const float4*>(Eb + (size_t)trow * kRow);
        Pq[0] = __ldg(r + lane);
        Pq[1] = __ldg(r + 32 + lane);
        Pq[2] = __ldg(r + 64 + lane);
    };

    auto rescale = [&]() {
        float m = a[0];
#pragma unroll
        for (int j = 1; j < 9; j++) m = fmaxf(m, a[j]);
        const bool nz = (m > 0.f);
        const int  e     = nz ? (((__float_as_int(m) >> 23) & 0xff) - 127) : 0;
        const int  cand  = nz ? (X + e) : NEGI;
        const int  candp = __shfl_up_sync(FULL, cand, 1);
        int Xn;
        if (lane == 0) {
            Xn = nz ? cand : X;
        } else {
            const int lower = (candp > NEGI) ? (candp - 24) : NEGI;
            const int ownc  = nz ? cand : NEGI;
            Xn = max(ownc, lower);
            if (Xn == NEGI) Xn = X;                // fully empty region: keep
        }
        float f1, f2;
        twoFactor(X - Xn, f1, f2);                 // rescale own values (split-safe)
#pragma unroll
        for (int j = 0; j < 9; j++) a[j] = (a[j] * f1) * f2;
        X = Xn;
        const int Xp = __shfl_up_sync(FULL, X, 1); // predecessor FINAL frame
        twoFactor(Xp - X, sD1, sD2);
        if (lane == 0) { sD1 = 0.f; sD2 = 0.f; }
    };

    // Main loop: invariant at head P[i] = emissions(row t+i), i=0..7.
    int t = 1;
    for (; t + 7 < Tb; t += 8) {
        dostep(P[0]); prefetch(P[0], min(t + 8,  kT - 1));
        dostep(P[1]); prefetch(P[1], min(t + 9,  kT - 1));
        dostep(P[2]); prefetch(P[2], min(t + 10, kT - 1));
        dostep(P[3]); prefetch(P[3], min(t + 11, kT - 1));
        rescale();
        dostep(P[4]); prefetch(P[4], min(t + 12, kT - 1));
        dostep(P[5]); prefetch(P[5], min(t + 13, kT - 1));
        dostep(P[6]); prefetch(P[6], min(t + 14, kT - 1));
        dostep(P[7]); prefetch(P[7], min(t + 15, kT - 1));
        rescale();
    }
    // Tail (<=7 steps): STATIC indices only — dynamic indexing would demote
    // the whole P ring to local memory.
    if (t < Tb) { dostep(P[0]); ++t; }
    if (t < Tb) { dostep(P[1]); ++t; }
    if (t < Tb) { dostep(P[2]); ++t; }
    if (t < Tb) { dostep(P[3]); ++t; }
    rescale();
    if (t < Tb) { dostep(P[4]); ++t; }
    if (t < Tb) { dostep(P[5]); ++t; }
    if (t < Tb) { dostep(P[6]); ++t; }

    // Final: combine alpha[2*len] and alpha[2*len-1] with per-lane exponents.
    __shared__ float Af[288];
    __shared__ int   Xf[32];
#pragma unroll
    for (int j = 0; j < 9; j++) Af[9 * lane + j] = a[j];
    Xf[lane] = X;
    __syncwarp();
    if (lane == 0) {
        const int sB = 2 * len, sL = sB - 1;
        const float aB = Af[sB], aL = Af[sL];
        const float yB = (aB > 0.f) ? (log2f(aB) + (float)Xf[sB / 9]) : -1e30f;
        const float yL = (aL > 0.f) ? (log2f(aL) + (float)Xf[sL / 9]) : -1e30f;
        const float mx = fmaxf(yB, yL);
        const float r  = mx + log2f(exp2f(yB - mx) + exp2f(yL - mx));
        g_nll[b] = -r * 0.69314718055994530942f;   // log2 -> ln
    }
}

// ---------------------------------------------------------------------------
// Kernel 3: mean over batch -> d_out[0]. Deterministic (no atomics).
// ---------------------------------------------------------------------------
__global__ void ctc_finish_kernel(float* __restrict__ out)
{
    float v = g_nll[threadIdx.x];
#pragma unroll
    for (int o = 16; o; o >>= 1) v += __shfl_xor_sync(0xffffffffu, v, o);
    if (threadIdx.x == 0) out[0] = v * (1.0f / kB);
}

extern "C" void kernel_launch(void* const* d_in, const int* in_sizes, int n_in,
                              void* d_out, int out_size)
{
    const int*   labels       = (const int*)d_in[0];
    const float* data         = (const float*)d_in[1];
    const int*   label_length = (const int*)d_in[2];
    const int*   data_length  = (const int*)d_in[3];
    float*       out          = (float*)d_out;

    ctc_emis_kernel<<<(kT * kB) / 8, 256>>>(data, labels);
    ctc_dp_kernel<<<kB, 32>>>(labels, label_length, data_length);
    ctc_finish_kernel<<<1, 32>>>(out);
}

// round 5
// speedup vs baseline: 2.7061x; 1.2281x over previous
#include <cuda_runtime.h>
#include <cuda_bf16.h>
#include <cstddef>

// Problem constants (CTCLoss_56298431315981): T=1024, B=32, C=1024, L=128
constexpr int kT = 1024;
constexpr int kB = 32;
constexpr int kC = 1024;
constexpr int kL = 128;
constexpr int kS = 2 * kL + 1;   // 257 extended states
constexpr int kRow = 384;        // floats per (b,t) row: 3 comps x 32 lanes x 4
constexpr int kTP = kT + 24;     // padded T so prefetch never needs clamping

// Scratch (static __device__ — no allocations allowed)
// Layout: float4 view [b][t][comp 0..2][lane 0..31]; lane-major per comp.
// comp2.y of every lane carries log2(row max prob) for renormalization.
__device__ float g_E2[(size_t)kB * kTP * kRow];
__device__ float g_nll[kB];

// ---------------------------------------------------------------------------
// 2^d as a product of two representable fp32 powers of two. |d|<=252 exact;
// d<-252 flushes to 0. Factors must stay separate (product can be inf;
// 0 * f1 * f2 must remain 0 for empty-lane halos).
// ---------------------------------------------------------------------------
__device__ __forceinline__ void twoFactor(int d, float& f1, float& f2)
{
    d = max(min(d, 252), -300);
    if (d < -252) { f1 = 0.f; f2 = 0.f; return; }
    const int dh = d / 2;  // trunc toward 0: both halves stay in [-126,126]
    f1 = __int_as_float((dh + 127) << 23);
    f2 = __int_as_float((d - dh + 127) << 23);
}

// ---------------------------------------------------------------------------
// Kernel 1: per-(t,b) softmax; write row-max-normalized linear probabilities
// in lane-major layout, plus log2(rowmax) in comp2.y. One warp per row.
// t-REVERSED block order: small-t rows are written last -> L2-hot for the DP.
// ---------------------------------------------------------------------------
__global__ void __launch_bounds__(256) ctc_emis_kernel(
    const float* __restrict__ data, const int* __restrict__ labels)
{
    __shared__ float sh[8][kC];
    __shared__ int   shlab[8][kL];
    const int warp = threadIdx.x >> 5;
    const int lane = threadIdx.x & 31;
    const int row  = (kT * kB - 1) - ((blockIdx.x << 3) + warp); // reversed
    const int t = row >> 5;                      // B == 32
    const int b = row & 31;

    reinterpret_cast<int4*>(shlab[warp])[lane] =
        reinterpret_cast<const int4*>(labels + b * kL)[lane];

    const float4* src = reinterpret_cast<const float4*>(data + (size_t)(t * kB + b) * kC);

    float m = -3.4e38f;
    float4 v[8];
#pragma unroll
    for (int i = 0; i < 8; i++) {
        v[i] = src[(i << 5) + lane];
        reinterpret_cast<float4*>(sh[warp])[(i << 5) + lane] = v[i];
        m = fmaxf(m, fmaxf(fmaxf(v[i].x, v[i].y), fmaxf(v[i].z, v[i].w)));
    }
#pragma unroll
    for (int o = 16; o; o >>= 1) m = fmaxf(m, __shfl_xor_sync(0xffffffffu, m, o));

    float ssum = 0.f;
#pragma unroll
    for (int i = 0; i < 8; i++) {
        ssum += __expf(v[i].x - m) + __expf(v[i].y - m) +
                __expf(v[i].z - m) + __expf(v[i].w - m);
    }
#pragma unroll
    for (int o = 16; o; o >>= 1) ssum += __shfl_xor_sync(0xffffffffu, ssum, o);

    const float lse = m + __logf(ssum);

    __syncwarp();  // smem stores (data row + labels) visible warp-wide

    const float blank = __expf(sh[warp][0] - lse);   // class 0 = blank
    float out[9];
#pragma unroll
    for (int j = 0; j < 9; j++) out[j] = 0.f;
    const int s0 = 9 * lane;
    float pmax = 0.f;
#pragma unroll
    for (int j = 0; j < 9; j++) {
        const int s = s0 + j;
        if (s < kS) {
            out[j] = (s & 1) ? __expf(sh[warp][shlab[warp][s >> 1]] - lse) : blank;
            pmax = fmaxf(pmax, out[j]);
        }
    }
#pragma unroll
    for (int o = 16; o; o >>= 1) pmax = fmaxf(pmax, __shfl_xor_sync(0xffffffffu, pmax, o));

    const float r   = __frcp_rn(pmax);
    const float lg2 = -__log2f(r);        // log2 of the factor we divided out
#pragma unroll
    for (int j = 0; j < 9; j++) out[j] *= r;

    float4* dst = reinterpret_cast<float4*>(g_E2 + ((size_t)b * kTP + t) * kRow);
    dst[lane]      = make_float4(out[0], out[1], out[2], out[3]);
    dst[32 + lane] = make_float4(out[4], out[5], out[6], out[7]);
    dst[64 + lane] = make_float4(out[8], lg2, 0.f, 0.f);
}

// ---------------------------------------------------------------------------
// Kernel 2: CTC forward DP, linear domain, per-lane block floating point with
// 2-lane frame-gap cap, rescale every 6 steps. One warp per batch element,
// lane l owns states [9l, 9l+9). No barriers, no MUFU, no local memory.
// ---------------------------------------------------------------------------
__global__ void __launch_bounds__(32) ctc_dp_kernel(
    const int* __restrict__ labels, const int* __restrict__ llen,
    const int* __restrict__ dlen)
{
    const unsigned FULL = 0xffffffffu;
    const int NEGI = -(1 << 28);
    const int b    = blockIdx.x;
    const int lane = threadIdx.x;

    const int len = llen[b];
    const int Tb  = dlen[b];               // 512..1024
    const float* __restrict__ Eb = g_E2 + (size_t)b * kTP * kRow;
    const int* __restrict__ lab  = labels + b * kL;

    float allow[9];
#pragma unroll
    for (int j = 0; j < 9; j++) {
        const int s = 9 * lane + j;
        bool al = false;
        if (s < kS && (s & 1) && s >= 3) al = (lab[s >> 1] != lab[(s >> 1) - 1]);
        allow[j] = al ? 1.0f : 0.0f;
    }

    float a[9];
#pragma unroll
    for (int j = 0; j < 9; j++) a[j] = 0.f;
    if (lane == 0) {
        a[0] = __ldg(&Eb[0]);    // t=0 state 0 (blank)
        a[1] = __ldg(&Eb[1]);    // t=0 state 1 (label0)
    }
    float lgsum = __ldg(&Eb[64 * 4 + 1]);  // t=0 row's log2(pmax) (comp2 lane0 .y)
    int   X   = 0;
    float sD1 = (lane == 0) ? 0.f : 1.f;   // halo frame factor = sD1*sD2 (keep split!)
    float sD2 = (lane == 0) ? 0.f : 1.f;

    // 12-deep emission prefetch ring (rows t=1..12; Tb >= 512 so all valid)
    float4 P[12][3];
#pragma unroll
    for (int q = 0; q < 12; q++) {
        const float4* r = reinterpret_cast<const float4*>(Eb + (size_t)(1 + q) * kRow);
        P[q][0] = __ldg(r + lane);
        P[q][1] = __ldg(r + 32 + lane);
        P[q][2] = __ldg(r + 64 + lane);
    }

    auto dostep = [&](const float4* Pq) {
        float h1 = __shfl_up_sync(FULL, a[8], 1);
        float h2 = __shfl_up_sync(FULL, a[7], 1);
        h1 = (h1 * sD1) * sD2;
        h2 = (h2 * sD1) * sD2;
        lgsum += Pq[2].y;                           // row log2(pmax)
        float na[9];
        na[0] = fmaf(allow[0], h2,   a[0] + h1)   * Pq[0].x;
        na[1] = fmaf(allow[1], h1,   a[1] + a[0]) * Pq[0].y;
        na[2] = fmaf(allow[2], a[0], a[2] + a[1]) * Pq[0].z;
        na[3] = fmaf(allow[3], a[1], a[3] + a[2]) * Pq[0].w;
        na[4] = fmaf(allow[4], a[2], a[4] + a[3]) * Pq[1].x;
        na[5] = fmaf(allow[5], a[3], a[5] + a[4]) * Pq[1].y;
        na[6] = fmaf(allow[6], a[4], a[6] + a[5]) * Pq[1].z;
        na[7] = fmaf(allow[7], a[5], a[7] + a[6]) * Pq[1].w;
        na[8] = fmaf(allow[8], a[6], a[8] + a[7]) * Pq[2].x;
#pragma unroll
        for (int j = 0; j < 9; j++) a[j] = na[j];
    };

    auto prefetch = [&](float4* Pq, int trow) {
        const float4* r = reinterpret_cast<const float4*>(Eb + (size_t)trow * kRow);
        Pq[0] = __ldg(r + lane);
        Pq[1] = __ldg(r + 32 + lane);
        Pq[2] = __ldg(r + 64 + lane);
    };

    // Rescale with 2-lane frame cap: alignment propagates 2 lanes per rescale,
    // wavefront moves 12 states = 1.33 lanes per 6-step period. 2 > 1.33.
    auto rescale = [&]() {
        float m = a[0];
#pragma unroll
        for (int j = 1; j < 9; j++) m = fmaxf(m, a[j]);
        const bool nz = (m > 0.f);
        const int  e    = nz ? (((__float_as_int(m) >> 23) & 0xff) - 127) : 0;
        const int  cand = nz ? (X + e) : NEGI;
        const int  c1 = __shfl_up_sync(FULL, cand, 1);
        const int  c2 = __shfl_up_sync(FULL, cand, 2);
        int Xn;
        if (lane == 0) {
            Xn = nz ? cand : X;
        } else {
            const int low  = max(c1 - 24, c2 - 48);
            const int ownc = nz ? cand : NEGI;
            Xn = max(ownc, low);
            if (Xn <= NEGI) Xn = X;                // fully empty region: keep
        }
        float f1, f2;
        twoFactor(X - Xn, f1, f2);                 // rescale own values (split-safe)
#pragma unroll
        for (int j = 0; j < 9; j++) a[j] = (a[j] * f1) * f2;
        X = Xn;
        const int Xp = __shfl_up_sync(FULL, X, 1); // predecessor FINAL frame
        twoFactor(Xp - X, sD1, sD2);
        if (lane == 0) { sD1 = 0.f; sD2 = 0.f; }
    };

    // Main loop: invariant at head P[i] = emissions(row t+i), i=0..11.
    int t = 1;
    for (; t + 11 < Tb; t += 12) {
        dostep(P[0]);  prefetch(P[0],  t + 12);
        dostep(P[1]);  prefetch(P[1],  t + 13);
        dostep(P[2]);  prefetch(P[2],  t + 14);
        dostep(P[3]);  prefetch(P[3],  t + 15);
        dostep(P[4]);  prefetch(P[4],  t + 16);
        dostep(P[5]);  prefetch(P[5],  t + 17);
        rescale();
        dostep(P[6]);  prefetch(P[6],  t + 18);
        dostep(P[7]);  prefetch(P[7],  t + 19);
        dostep(P[8]);  prefetch(P[8],  t + 20);
        dostep(P[9]);  prefetch(P[9],  t + 21);
        dostep(P[10]); prefetch(P[10], t + 22);
        dostep(P[11]); prefetch(P[11], t + 23);
        rescale();
    }
    // Tail (<=11 steps): STATIC indices only (dynamic indexing of P would
    // demote the whole ring to local memory).
    if (t < Tb) { dostep(P[0]); ++t; }
    if (t < Tb) { dostep(P[1]); ++t; }
    if (t < Tb) { dostep(P[2]); ++t; }
    if (t < Tb) { dostep(P[3]); ++t; }
    rescale();
    if (t < Tb) { dostep(P[4]); ++t; }
    if (t < Tb) { dostep(P[5]); ++t; }
    if (t < Tb) { dostep(P[6]); ++t; }
    if (t < Tb) { dostep(P[7]); ++t; }
    rescale();
    if (t < Tb) { dostep(P[8]); ++t; }
    if (t < Tb) { dostep(P[9]); ++t; }
    if (t < Tb) { dostep(P[10]); ++t; }

    // Final: combine alpha[2*len] and alpha[2*len-1]; add back row log2 sums.
    __shared__ float Af[288];
    __shared__ int   Xf[32];
#pragma unroll
    for (int j = 0; j < 9; j++) Af[9 * lane + j] = a[j];
    Xf[lane] = X;
    __syncwarp();
    if (lane == 0) {
        const int sB = 2 * len, sL = sB - 1;
        const float aB = Af[sB], aL = Af[sL];
        const float yB = (aB > 0.f) ? (log2f(aB) + (float)Xf[sB / 9]) : -1e30f;
        const float yL = (aL > 0.f) ? (log2f(aL) + (float)Xf[sL / 9]) : -1e30f;
        const float mx = fmaxf(yB, yL);
        const float rr = mx + log2f(exp2f(yB - mx) + exp2f(yL - mx)) + lgsum;
        g_nll[b] = -rr * 0.69314718055994530942f;   // log2 -> ln
    }
}

// ---------------------------------------------------------------------------
// Kernel 3: mean over batch -> d_out[0]. Deterministic (no atomics).
// ---------------------------------------------------------------------------
__global__ void ctc_finish_kernel(float* __restrict__ out)
{
    float v = g_nll[threadIdx.x];
#pragma unroll
    for (int o = 16; o; o >>= 1) v += __shfl_xor_sync(0xffffffffu, v, o);
    if (threadIdx.x == 0) out[0] = v * (1.0f / kB);
}

extern "C" void kernel_launch(void* const* d_in, const int* in_sizes, int n_in,
                              void* d_out, int out_size)
{
    const int*   labels       = (const int*)d_in[0];
    const float* data         = (const float*)d_in[1];
    const int*   label_length = (const int*)d_in[2];
    const int*   data_length  = (const int*)d_in[3];
    float*       out          = (float*)d_out;

    ctc_emis_kernel<<<(kT * kB) / 8, 256>>>(data, labels);
    ctc_dp_kernel<<<kB, 32>>>(labels, label_length, data_length);
    ctc_finish_kernel<<<1, 32>>>(out);
}